// round 12
// baseline (speedup 1.0000x reference)
#include <cuda_runtime.h>
#include <cuda_bf16.h>
#include <mma.h>
#include <math.h>
#include <stdint.h>

using namespace nvcuda;

// Problem constants
#define CIN    512
#define COUT1  1024
#define NBATCH 32
#define K1     4608          // CIN*9
#define MTOT   32768         // NBATCH*32*32
#define COUT2  425
#define N2PAD  512
#define K2     1024

#define KC     32
#define NKT1   (K1 / KC)     // 144
#define NKT2   (K2 / KC)     // 32

// conv1 smem (bf16 elements): A [k][m] pitch 136 (32 rows), B [n][k] pitch 40 (128 rows)
#define C1_PM      136
#define C1_PK      40
#define C1_AHI     0
#define C1_ALO     4352
#define C1_BHI     8704
#define C1_BLO     13824
#define C1_STAGE   18944
#define C1_SMEM_B  (3 * C1_STAGE * 2)     // 113664 bytes -> 2 CTAs/SM

// conv2 smem: A [k][m] pitch 136, B [k][n] pitch 136, 3 stages
#define C2_SAM     136
#define C2_SBN     136
#define C2_AHI     0
#define C2_ALO     4352
#define C2_BHI     8704
#define C2_BLO     13056
#define C2_STAGE   17408
#define C2_SMEM_B  (3 * C2_STAGE * 2)     // 104448 bytes -> 2 CTAs/SM

// Scratch (static device memory)
__device__ __align__(16) __nv_bfloat16 g_ahi[(size_t)K1 * MTOT];   // im2col A, [k][m]
__device__ __align__(16) __nv_bfloat16 g_alo[(size_t)K1 * MTOT];
__device__ __align__(16) __nv_bfloat16 g_w1hi[(size_t)COUT1 * K1]; // [n][k]
__device__ __align__(16) __nv_bfloat16 g_w1lo[(size_t)COUT1 * K1];
__device__ __align__(16) __nv_bfloat16 g_xhi[(size_t)COUT1 * MTOT]; // [k][m]
__device__ __align__(16) __nv_bfloat16 g_xlo[(size_t)COUT1 * MTOT];
__device__ __align__(16) __nv_bfloat16 g_w2hi[(size_t)K2 * N2PAD];  // [k][n]
__device__ __align__(16) __nv_bfloat16 g_w2lo[(size_t)K2 * N2PAD];
__device__ float g_p[(size_t)MTOT * COUT2];                         // [m][n]

__constant__ float c_anc_w[5] = {42.f, 98.f, 180.f, 300.f, 400.f};
__constant__ float c_anc_h[5] = {45.f, 130.f, 260.f, 180.f, 400.f};

__device__ __forceinline__ void split_bf16(float v, unsigned short& h, unsigned short& l) {
    __nv_bfloat16 hb = __float2bfloat16_rn(v);
    h = __bfloat16_as_ushort(hb);
    l = __bfloat16_as_ushort(__float2bfloat16_rn(v - __bfloat162float(hb)));
}

__device__ __forceinline__ void cp16(const __nv_bfloat16* smem_dst, const void* gsrc) {
    uint32_t s = (uint32_t)__cvta_generic_to_shared(smem_dst);
    asm volatile("cp.async.cg.shared.global [%0], [%1], 16;" :: "r"(s), "l"(gsrc));
}
__device__ __forceinline__ void cp_commit() {
    asm volatile("cp.async.commit_group;" ::: "memory");
}
template <int N>
__device__ __forceinline__ void cp_wait() {
    asm volatile("cp.async.wait_group %0;" :: "n"(N) : "memory");
}

// ---------------------------------------------------------------------------
// Weight prep
// ---------------------------------------------------------------------------
__global__ void k_split_w1(const float* __restrict__ w,
                           const float* __restrict__ gma,
                           const float* __restrict__ var) {
    int idx = blockIdx.x * 256 + threadIdx.x;
    if (idx >= COUT1 * K1) return;
    int n = idx / K1;
    float scale = gma[n] * rsqrtf(var[n] + 1e-5f);
    float v = w[idx] * scale;
    unsigned short h, l;
    split_bf16(v, h, l);
    g_w1hi[idx] = __ushort_as_bfloat16(h);
    g_w1lo[idx] = __ushort_as_bfloat16(l);
}

__global__ void k_split_w2(const float* __restrict__ w) {
    __shared__ float tile[32][33];
    int kb = blockIdx.x * 32, nb = blockIdx.y * 32;
    int txd = threadIdx.x, tyd = threadIdx.y;
#pragma unroll
    for (int r = 0; r < 4; r++) {
        int n = nb + tyd + r * 8;
        tile[tyd + r * 8][txd] = (n < COUT2) ? w[(size_t)n * K2 + kb + txd] : 0.0f;
    }
    __syncthreads();
    int n = nb + txd;
#pragma unroll
    for (int r = 0; r < 4; r++) {
        int k = kb + tyd + r * 8;
        unsigned short h, l;
        split_bf16(tile[txd][tyd + r * 8], h, l);
        g_w2hi[(size_t)k * N2PAD + n] = __ushort_as_bfloat16(h);
        g_w2lo[(size_t)k * N2PAD + n] = __ushort_as_bfloat16(l);
    }
}

// ---------------------------------------------------------------------------
// im2col: feat [B][C][32][32] fp32 -> g_ahi/g_alo [k][m] bf16 (zero-padded 3x3)
// ---------------------------------------------------------------------------
__global__ __launch_bounds__(256)
void k_im2col(const float* __restrict__ feat) {
    int k = blockIdx.y;
    int c = k / 9;
    int q = k - 9 * c;
    int r = q / 3;
    int s = q - 3 * r;
    int m8 = (blockIdx.x * 256 + threadIdx.x) * 8;
    int img = m8 >> 10;
    int pos = m8 & 1023;
    int y = pos >> 5, x = pos & 31;
    int iy = y + r - 1;
    bool rowok = (unsigned)iy < 32u;
    const float* row = feat + (((size_t)img * CIN + c) << 10) + (iy << 5);
    uint4 hv, lv;
    unsigned short* hp = (unsigned short*)&hv;
    unsigned short* lp = (unsigned short*)&lv;
#pragma unroll
    for (int t = 0; t < 8; t++) {
        int ix = x + s - 1 + t;
        float v = (rowok && (unsigned)ix < 32u) ? row[ix] : 0.0f;
        split_bf16(v, hp[t], lp[t]);
    }
    size_t o = (size_t)k * MTOT + m8;
    *(uint4*)(g_ahi + o) = hv;
    *(uint4*)(g_alo + o) = lv;
}

// ---------------------------------------------------------------------------
// Conv1: wmma bf16x3 GEMM. CTA 128x128, 256 thr, warp 64x32, KC=32,
// 3-stage cp.async (wait<1>), 2 CTAs/SM. blockIdx.x = n-tile (L2 reuse).
// ---------------------------------------------------------------------------
__global__ __launch_bounds__(256, 2)
void k_conv1_wm(const float* __restrict__ gma, const float* __restrict__ bet,
                const float* __restrict__ mea, const float* __restrict__ var) {
    extern __shared__ __align__(16) char smraw[];
    __nv_bfloat16* smb = (__nv_bfloat16*)smraw;
    float* smf = (float*)smraw;

    const int tid = threadIdx.x;
    const int w = tid >> 5;
    const int wm = w & 1, wn = w >> 1;
    const int n0 = blockIdx.x * 128;
    const int m0 = blockIdx.y * 128;

    const int akr = tid >> 3;            // 0..31
    const int aseg = (tid & 7) * 16;
    const int brow = tid >> 1;           // 0..127
    const int bq = (tid & 1) * 16;

    wmma::fragment<wmma::accumulator, 16, 16, 16, float> acc[4][2];
#pragma unroll
    for (int i = 0; i < 4; i++)
#pragma unroll
        for (int j = 0; j < 2; j++) wmma::fill_fragment(acc[i][j], 0.0f);

    auto loadStage = [&](int st, int kc) {
        __nv_bfloat16* base = smb + st * C1_STAGE;
        size_t ga = (size_t)(kc + akr) * MTOT + m0 + aseg;
        cp16(base + C1_AHI + akr * C1_PM + aseg,     g_ahi + ga);
        cp16(base + C1_AHI + akr * C1_PM + aseg + 8, g_ahi + ga + 8);
        cp16(base + C1_ALO + akr * C1_PM + aseg,     g_alo + ga);
        cp16(base + C1_ALO + akr * C1_PM + aseg + 8, g_alo + ga + 8);
        size_t gb = (size_t)(n0 + brow) * K1 + kc + bq;
        cp16(base + C1_BHI + brow * C1_PK + bq,     g_w1hi + gb);
        cp16(base + C1_BHI + brow * C1_PK + bq + 8, g_w1hi + gb + 8);
        cp16(base + C1_BLO + brow * C1_PK + bq,     g_w1lo + gb);
        cp16(base + C1_BLO + brow * C1_PK + bq + 8, g_w1lo + gb + 8);
    };

    auto compute = [&](int st) {
        const __nv_bfloat16* base = smb + st * C1_STAGE;
#pragma unroll
        for (int kk = 0; kk < KC; kk += 16) {
            wmma::fragment<wmma::matrix_a, 16, 16, 16, __nv_bfloat16, wmma::col_major> af[4];
            wmma::fragment<wmma::matrix_b, 16, 16, 16, __nv_bfloat16, wmma::col_major> bhf[2], blf[2];
#pragma unroll
            for (int i = 0; i < 4; i++)
                wmma::load_matrix_sync(af[i], base + C1_AHI + kk * C1_PM + wm * 64 + i * 16, C1_PM);
#pragma unroll
            for (int j = 0; j < 2; j++)
                wmma::load_matrix_sync(bhf[j], base + C1_BHI + (wn * 32 + j * 16) * C1_PK + kk, C1_PK);
#pragma unroll
            for (int i = 0; i < 4; i++)
#pragma unroll
                for (int j = 0; j < 2; j++)
                    wmma::mma_sync(acc[i][j], af[i], bhf[j], acc[i][j]);
#pragma unroll
            for (int j = 0; j < 2; j++)
                wmma::load_matrix_sync(blf[j], base + C1_BLO + (wn * 32 + j * 16) * C1_PK + kk, C1_PK);
#pragma unroll
            for (int i = 0; i < 4; i++)
#pragma unroll
                for (int j = 0; j < 2; j++)
                    wmma::mma_sync(acc[i][j], af[i], blf[j], acc[i][j]);
#pragma unroll
            for (int i = 0; i < 4; i++)
                wmma::load_matrix_sync(af[i], base + C1_ALO + kk * C1_PM + wm * 64 + i * 16, C1_PM);
#pragma unroll
            for (int i = 0; i < 4; i++)
#pragma unroll
                for (int j = 0; j < 2; j++)
                    wmma::mma_sync(acc[i][j], af[i], bhf[j], acc[i][j]);
        }
    };

    loadStage(0, 0);
    cp_commit();
    loadStage(1, KC);
    cp_commit();
    for (int kt = 0; kt < NKT1; kt++) {
        if (kt < NKT1 - 1) cp_wait<1>(); else cp_wait<0>();
        __syncthreads();
        if (kt + 2 < NKT1) {
            loadStage((kt + 2) % 3, (kt + 2) * KC);
            cp_commit();
        }
        compute(kt % 3);
    }

    // Epilogue: acc -> smem col-major (element (m,n) at smf[n*128+m])
    __syncthreads();
#pragma unroll
    for (int i = 0; i < 4; i++)
#pragma unroll
        for (int j = 0; j < 2; j++)
            wmma::store_matrix_sync(smf + (wn * 32 + j * 16) * 128 + wm * 64 + i * 16,
                                    acc[i][j], 128, wmma::mem_col_major);
    __syncthreads();

    // BN + leaky, split to bf16 hi/lo, store [k][m]
#pragma unroll
    for (int it = 0; it < 16; it++) {
        int id = it * 256 + tid;
        int ncol = id >> 5;           // 0..127
        int r4 = (id & 31) * 4;       // 0..124
        float4 v = *(const float4*)(smf + ncol * 128 + r4);
        int n = n0 + ncol;
        float scale = gma[n] * rsqrtf(var[n] + 1e-5f);
        float bias = bet[n] - mea[n] * scale;
        float t;
        unsigned short h[4], l[4];
        t = v.x + bias; t = t > 0.f ? t : 0.1f * t; split_bf16(t, h[0], l[0]);
        t = v.y + bias; t = t > 0.f ? t : 0.1f * t; split_bf16(t, h[1], l[1]);
        t = v.z + bias; t = t > 0.f ? t : 0.1f * t; split_bf16(t, h[2], l[2]);
        t = v.w + bias; t = t > 0.f ? t : 0.1f * t; split_bf16(t, h[3], l[3]);
        size_t go = (size_t)n * MTOT + m0 + r4;
        *(uint2*)(g_xhi + go) = *(const uint2*)h;
        *(uint2*)(g_xlo + go) = *(const uint2*)l;
    }
}

// ---------------------------------------------------------------------------
// Conv2: wmma bf16x3 GEMM. CTA 128x128, 256 thr, warp 64x32, KC=32,
// 3-stage cp.async (wait<1>), 2 CTAs/SM. blockIdx.x = n-tile.
// ---------------------------------------------------------------------------
__global__ __launch_bounds__(256, 2)
void k_conv2_wm(const float* __restrict__ bias2) {
    extern __shared__ __align__(16) char smraw[];
    __nv_bfloat16* smb = (__nv_bfloat16*)smraw;
    float* smf = (float*)smraw;

    const int tid = threadIdx.x;
    const int w = tid >> 5;
    const int wm = w & 1, wn = w >> 1;
    const int n0 = blockIdx.x * 128;
    const int m0 = blockIdx.y * 128;

    const int akr = tid >> 3;            // 0..31
    const int aseg = (tid & 7) * 16;
    const int bkr = tid >> 3;
    const int bseg = (tid & 7) * 16;

    wmma::fragment<wmma::accumulator, 16, 16, 16, float> acc[4][2];
#pragma unroll
    for (int i = 0; i < 4; i++)
#pragma unroll
        for (int j = 0; j < 2; j++) wmma::fill_fragment(acc[i][j], 0.0f);

    auto loadStage = [&](int st, int kc) {
        __nv_bfloat16* base = smb + st * C2_STAGE;
        size_t ga = (size_t)(kc + akr) * MTOT + m0 + aseg;
        cp16(base + C2_AHI + akr * C2_SAM + aseg,     g_xhi + ga);
        cp16(base + C2_AHI + akr * C2_SAM + aseg + 8, g_xhi + ga + 8);
        cp16(base + C2_ALO + akr * C2_SAM + aseg,     g_xlo + ga);
        cp16(base + C2_ALO + akr * C2_SAM + aseg + 8, g_xlo + ga + 8);
        size_t gb = (size_t)(kc + bkr) * N2PAD + n0 + bseg;
        cp16(base + C2_BHI + bkr * C2_SBN + bseg,     g_w2hi + gb);
        cp16(base + C2_BHI + bkr * C2_SBN + bseg + 8, g_w2hi + gb + 8);
        cp16(base + C2_BLO + bkr * C2_SBN + bseg,     g_w2lo + gb);
        cp16(base + C2_BLO + bkr * C2_SBN + bseg + 8, g_w2lo + gb + 8);
    };

    auto compute = [&](int st) {
        const __nv_bfloat16* base = smb + st * C2_STAGE;
#pragma unroll
        for (int kk = 0; kk < KC; kk += 16) {
            wmma::fragment<wmma::matrix_a, 16, 16, 16, __nv_bfloat16, wmma::col_major> af[4];
            wmma::fragment<wmma::matrix_b, 16, 16, 16, __nv_bfloat16, wmma::row_major> bhf[2], blf[2];
#pragma unroll
            for (int i = 0; i < 4; i++)
                wmma::load_matrix_sync(af[i], base + C2_AHI + kk * C2_SAM + wm * 64 + i * 16, C2_SAM);
#pragma unroll
            for (int j = 0; j < 2; j++)
                wmma::load_matrix_sync(bhf[j], base + C2_BHI + kk * C2_SBN + wn * 32 + j * 16, C2_SBN);
#pragma unroll
            for (int i = 0; i < 4; i++)
#pragma unroll
                for (int j = 0; j < 2; j++)
                    wmma::mma_sync(acc[i][j], af[i], bhf[j], acc[i][j]);
#pragma unroll
            for (int j = 0; j < 2; j++)
                wmma::load_matrix_sync(blf[j], base + C2_BLO + kk * C2_SBN + wn * 32 + j * 16, C2_SBN);
#pragma unroll
            for (int i = 0; i < 4; i++)
#pragma unroll
                for (int j = 0; j < 2; j++)
                    wmma::mma_sync(acc[i][j], af[i], blf[j], acc[i][j]);
#pragma unroll
            for (int i = 0; i < 4; i++)
                wmma::load_matrix_sync(af[i], base + C2_ALO + kk * C2_SAM + wm * 64 + i * 16, C2_SAM);
#pragma unroll
            for (int i = 0; i < 4; i++)
#pragma unroll
                for (int j = 0; j < 2; j++)
                    wmma::mma_sync(acc[i][j], af[i], bhf[j], acc[i][j]);
        }
    };

    loadStage(0, 0);
    cp_commit();
    loadStage(1, KC);
    cp_commit();
    for (int kt = 0; kt < NKT2; kt++) {
        if (kt < NKT2 - 1) cp_wait<1>(); else cp_wait<0>();
        __syncthreads();
        if (kt + 2 < NKT2) {
            loadStage((kt + 2) % 3, (kt + 2) * KC);
            cp_commit();
        }
        compute(kt % 3);
    }

    // Epilogue: acc -> smem row-major (element (m,n) at smf[m*128+n]), + bias -> g_p
    __syncthreads();
#pragma unroll
    for (int i = 0; i < 4; i++)
#pragma unroll
        for (int j = 0; j < 2; j++)
            wmma::store_matrix_sync(smf + (wm * 64 + i * 16) * 128 + wn * 32 + j * 16,
                                    acc[i][j], 128, wmma::mem_row_major);
    __syncthreads();

#pragma unroll
    for (int it = 0; it < 16; it++) {
        int id = it * 256 + tid;
        int mrow = id >> 5;          // 0..127
        int nc4 = (id & 31) * 4;
        float4 v = *(const float4*)(smf + mrow * 128 + nc4);
        int n = n0 + nc4;
        float* dst = g_p + (size_t)(m0 + mrow) * COUT2 + n;
        if (n + 0 < COUT2) dst[0] = v.x + bias2[n + 0];
        if (n + 1 < COUT2) dst[1] = v.y + bias2[n + 1];
        if (n + 2 < COUT2) dst[2] = v.z + bias2[n + 2];
        if (n + 3 < COUT2) dst[3] = v.w + bias2[n + 3];
    }
}

// ---------------------------------------------------------------------------
// Decode: one warp per (position, anchor)
// ---------------------------------------------------------------------------
__global__ void k_decode(float* __restrict__ out) {
    int g = blockIdx.x * (blockDim.x >> 5) + (threadIdx.x >> 5);
    int lane = threadIdx.x & 31;
    if (g >= MTOT * 5) return;
    int m = g / 5;
    int a = g - m * 5;
    const float* base = g_p + (size_t)m * COUT2 + a * 85;

    float t0 = base[0], t1 = base[1], t2 = base[2], t3 = base[3], t4 = base[4];

    float l0 = base[5 + lane];
    float l1 = base[5 + 32 + lane];
    float best = l0; int bi = lane;
    if (l1 > best) { best = l1; bi = lane + 32; }
    float l2 = -3.4e38f;
    if (lane < 16) {
        l2 = base[5 + 64 + lane];
        if (l2 > best) { best = l2; bi = lane + 64; }
    }
#pragma unroll
    for (int off = 16; off; off >>= 1) {
        float ob = __shfl_down_sync(0xffffffffu, best, off);
        int   oi = __shfl_down_sync(0xffffffffu, bi, off);
        if (ob > best || (ob == best && oi < bi)) { best = ob; bi = oi; }
    }
    float mx = __shfl_sync(0xffffffffu, best, 0);
    int gidx = __shfl_sync(0xffffffffu, bi, 0);

    float s = expf(l0 - mx) + expf(l1 - mx) + ((lane < 16) ? expf(l2 - mx) : 0.f);
#pragma unroll
    for (int off = 16; off; off >>= 1)
        s += __shfl_down_sync(0xffffffffu, s, off);

    if (lane == 0) {
        float bx = 1.f / (1.f + expf(-t0));
        float by = 1.f / (1.f + expf(-t1));
        float bw = expf(fminf(t2, 8.f));
        float bh = expf(fminf(t3, 8.f));
        float obj = 1.f / (1.f + expf(-t4));
        float score = obj / s;

        int b = m >> 10;
        int pos = m & 1023;
        int gy = pos >> 5, gx = pos & 31;
        float cx = (bx + (float)gx) * 32.f;
        float cy = (by + (float)gy) * 32.f;
        float pw = c_anc_w[a] * bw;
        float ph = c_anc_h[a] * bh;
        float x1 = fminf(fmaxf(cx - 0.5f * pw, 0.f), 1023.f);
        float y1 = fminf(fmaxf(cy - 0.5f * ph, 0.f), 1023.f);
        float x2 = fminf(fmaxf(cx + 0.5f * pw, 0.f), 1023.f);
        float y2 = fminf(fmaxf(cy + 0.5f * ph, 0.f), 1023.f);

        int idxo = pos * 5 + a;
        float* o5 = out + ((size_t)b * 5120 + idxo) * 5;
        o5[0] = x1; o5[1] = y1; o5[2] = x2; o5[3] = y2; o5[4] = score;
        out[(size_t)NBATCH * 5120 * 5 + (size_t)b * 5120 + idxo] = (float)gidx;
    }
}

// ---------------------------------------------------------------------------
extern "C" void kernel_launch(void* const* d_in, const int* in_sizes, int n_in,
                              void* d_out, int out_size) {
    const float* feat = (const float*)d_in[0];
    const float* w1   = (const float*)d_in[1];
    const float* gma  = (const float*)d_in[2];
    const float* bet  = (const float*)d_in[3];
    const float* mea  = (const float*)d_in[4];
    const float* var  = (const float*)d_in[5];
    const float* w2   = (const float*)d_in[6];
    const float* b2   = (const float*)d_in[7];
    float* out = (float*)d_out;

    static int attr_set = 0;
    if (!attr_set) {
        cudaFuncSetAttribute(k_conv1_wm, cudaFuncAttributeMaxDynamicSharedMemorySize, C1_SMEM_B);
        cudaFuncSetAttribute(k_conv2_wm, cudaFuncAttributeMaxDynamicSharedMemorySize, C2_SMEM_B);
        attr_set = 1;
    }

    k_split_w1<<<(COUT1 * K1 + 255) / 256, 256>>>(w1, gma, var);
    k_split_w2<<<dim3(K2 / 32, N2PAD / 32), dim3(32, 8)>>>(w2);
    k_im2col<<<dim3(MTOT / (8 * 256), K1), 256>>>(feat);
    k_conv1_wm<<<dim3(COUT1 / 128, MTOT / 128), 256, C1_SMEM_B>>>(gma, bet, mea, var);
    k_conv2_wm<<<dim3(N2PAD / 128, MTOT / 128), 256, C2_SMEM_B>>>(b2);
    k_decode<<<(MTOT * 5 * 32 + 255) / 256, 256>>>(out);
}

// round 14
// speedup vs baseline: 1.0389x; 1.0389x over previous
#include <cuda_runtime.h>
#include <cuda_bf16.h>
#include <mma.h>
#include <math.h>
#include <stdint.h>

using namespace nvcuda;

// Problem constants
#define CIN    512
#define COUT1  1024
#define NBATCH 32
#define K1     4608          // CIN*9
#define MTOT   32768         // NBATCH*32*32
#define COUT2  425
#define N2PAD  512
#define K2     1024

#define KC     32
#define NKT1   (K1 / KC)     // 144
#define NKT2   (K2 / KC)     // 32

// conv1 smem (bf16 elements): A [m][k] pitch 40 (128 rows), B [n][k] pitch 40 (128 rows)
#define C1_SA      40
#define C1_AHI     0
#define C1_ALO     5120
#define C1_BHI     10240
#define C1_BLO     15360
#define C1_STAGE   20480
#define C1_SMEM_B  (2 * C1_STAGE * 2)     // 81920 bytes -> 2 CTAs/SM

// conv2 smem: A [k][m] pitch 136, B [k][n] pitch 136, 2 stages
#define C2_SAM     136
#define C2_SBN     136
#define C2_AHI     0
#define C2_ALO     4352
#define C2_BHI     8704
#define C2_BLO     13056
#define C2_STAGE   17408
#define C2_SMEM_B  (2 * C2_STAGE * 2)     // 69632 bytes -> 2 CTAs/SM

// Scratch (static device memory)
__device__ __align__(16) __nv_bfloat16 g_w1hi[(size_t)COUT1 * K1]; // [n][k]
__device__ __align__(16) __nv_bfloat16 g_w1lo[(size_t)COUT1 * K1];
__device__ __align__(16) __nv_bfloat16 g_xhi[(size_t)COUT1 * MTOT]; // [k][m]
__device__ __align__(16) __nv_bfloat16 g_xlo[(size_t)COUT1 * MTOT];
__device__ __align__(16) __nv_bfloat16 g_w2hi[(size_t)K2 * N2PAD];  // [k][n]
__device__ __align__(16) __nv_bfloat16 g_w2lo[(size_t)K2 * N2PAD];
__device__ float g_p[(size_t)MTOT * COUT2];                         // [m][n]

__constant__ float c_anc_w[5] = {42.f, 98.f, 180.f, 300.f, 400.f};
__constant__ float c_anc_h[5] = {45.f, 130.f, 260.f, 180.f, 400.f};

__device__ __forceinline__ void split_bf16(float v, unsigned short& h, unsigned short& l) {
    __nv_bfloat16 hb = __float2bfloat16_rn(v);
    h = __bfloat16_as_ushort(hb);
    l = __bfloat16_as_ushort(__float2bfloat16_rn(v - __bfloat162float(hb)));
}

__device__ __forceinline__ void cp16(const __nv_bfloat16* smem_dst, const void* gsrc) {
    uint32_t s = (uint32_t)__cvta_generic_to_shared(smem_dst);
    asm volatile("cp.async.cg.shared.global [%0], [%1], 16;" :: "r"(s), "l"(gsrc));
}
__device__ __forceinline__ void cp_commit() {
    asm volatile("cp.async.commit_group;" ::: "memory");
}
template <int N>
__device__ __forceinline__ void cp_wait() {
    asm volatile("cp.async.wait_group %0;" :: "n"(N) : "memory");
}

// ---------------------------------------------------------------------------
// Weight prep
// ---------------------------------------------------------------------------
__global__ void k_split_w1(const float* __restrict__ w,
                           const float* __restrict__ gma,
                           const float* __restrict__ var) {
    int idx = blockIdx.x * 256 + threadIdx.x;
    if (idx >= COUT1 * K1) return;
    int n = idx / K1;
    float scale = gma[n] * rsqrtf(var[n] + 1e-5f);
    float v = w[idx] * scale;
    unsigned short h, l;
    split_bf16(v, h, l);
    g_w1hi[idx] = __ushort_as_bfloat16(h);
    g_w1lo[idx] = __ushort_as_bfloat16(l);
}

__global__ void k_split_w2(const float* __restrict__ w) {
    __shared__ float tile[32][33];
    int kb = blockIdx.x * 32, nb = blockIdx.y * 32;
    int txd = threadIdx.x, tyd = threadIdx.y;
#pragma unroll
    for (int r = 0; r < 4; r++) {
        int n = nb + tyd + r * 8;
        tile[tyd + r * 8][txd] = (n < COUT2) ? w[(size_t)n * K2 + kb + txd] : 0.0f;
    }
    __syncthreads();
    int n = nb + txd;
#pragma unroll
    for (int r = 0; r < 4; r++) {
        int k = kb + tyd + r * 8;
        unsigned short h, l;
        split_bf16(tile[txd][tyd + r * 8], h, l);
        g_w2hi[(size_t)k * N2PAD + n] = __ushort_as_bfloat16(h);
        g_w2lo[(size_t)k * N2PAD + n] = __ushort_as_bfloat16(l);
    }
}

// ---------------------------------------------------------------------------
// Conv1: wmma bf16x3 implicit GEMM with fused im2col gather.
// CTA 128x128, 256 thr (8 warps), warp 64x32, KC=32, 2-stage, 2 CTAs/SM.
// blockIdx.x = n-tile (fastest -> B tiles L2-resident, feat slices L2-shared).
// ---------------------------------------------------------------------------
__global__ __launch_bounds__(256, 2)
void k_conv1_wm(const float* __restrict__ feat,
                const float* __restrict__ gma, const float* __restrict__ bet,
                const float* __restrict__ mea, const float* __restrict__ var) {
    extern __shared__ __align__(16) char smraw[];
    __nv_bfloat16* smb = (__nv_bfloat16*)smraw;
    float* smf = (float*)smraw;

    const int tid = threadIdx.x;
    const int w = tid >> 5;
    const int wm = w & 1, wn = w >> 1;     // wm: 2 x 64-m, wn: 4 x 32-n
    const int n0 = blockIdx.x * 128;
    const int m0 = blockIdx.y * 128;

    // A gather: 2 threads per m-row, 16 k each (2 chunks of 8)
    const int arow = tid >> 1;
    const int ks = (tid & 1) * 16;
    const int m = m0 + arow;
    const int bimg = m >> 10;
    const int pos = m & 1023;
    const int ay = pos >> 5, ax = pos & 31;
    const float* fbase = feat + ((size_t)bimg * CIN << 10);

    // B cp.async: 2 threads per n-row, 16 k (two 16B chunks) each
    const int brow = tid >> 1;
    const int bq = (tid & 1) * 16;

    wmma::fragment<wmma::accumulator, 16, 16, 16, float> acc[4][2];
#pragma unroll
    for (int i = 0; i < 4; i++)
#pragma unroll
        for (int j = 0; j < 2; j++) wmma::fill_fragment(acc[i][j], 0.0f);

    auto loadStage = [&](int st, int kc) {
        __nv_bfloat16* base = smb + st * C1_STAGE;
#pragma unroll
        for (int h = 0; h < 2; h++) {
            int k0 = ks + h * 8;
            uint4 hv, lv;
            unsigned short* hp = (unsigned short*)&hv;
            unsigned short* lp = (unsigned short*)&lv;
#pragma unroll
            for (int j = 0; j < 8; j++) {
                int k = kc + k0 + j;
                int c = k / 9;
                int q = k - 9 * c;
                int r = q / 3;
                int s = q - 3 * r;
                int iy = ay + r - 1, ix = ax + s - 1;
                float v = 0.f;
                if ((unsigned)iy < 32u && (unsigned)ix < 32u)
                    v = fbase[(c << 10) + (iy << 5) + ix];
                split_bf16(v, hp[j], lp[j]);
            }
            *(uint4*)(base + C1_AHI + arow * C1_SA + k0) = hv;
            *(uint4*)(base + C1_ALO + arow * C1_SA + k0) = lv;
        }
        size_t gb = (size_t)(n0 + brow) * K1 + kc + bq;
        cp16(base + C1_BHI + brow * C1_SA + bq,     g_w1hi + gb);
        cp16(base + C1_BHI + brow * C1_SA + bq + 8, g_w1hi + gb + 8);
        cp16(base + C1_BLO + brow * C1_SA + bq,     g_w1lo + gb);
        cp16(base + C1_BLO + brow * C1_SA + bq + 8, g_w1lo + gb + 8);
    };

    auto compute = [&](int st) {
        const __nv_bfloat16* base = smb + st * C1_STAGE;
#pragma unroll
        for (int kk = 0; kk < KC; kk += 16) {
            wmma::fragment<wmma::matrix_a, 16, 16, 16, __nv_bfloat16, wmma::row_major> af[4];
            wmma::fragment<wmma::matrix_b, 16, 16, 16, __nv_bfloat16, wmma::col_major> bhf[2], blf[2];
#pragma unroll
            for (int i = 0; i < 4; i++)
                wmma::load_matrix_sync(af[i], base + C1_AHI + (wm * 64 + i * 16) * C1_SA + kk, C1_SA);
#pragma unroll
            for (int j = 0; j < 2; j++)
                wmma::load_matrix_sync(bhf[j], base + C1_BHI + (wn * 32 + j * 16) * C1_SA + kk, C1_SA);
#pragma unroll
            for (int i = 0; i < 4; i++)
#pragma unroll
                for (int j = 0; j < 2; j++)
                    wmma::mma_sync(acc[i][j], af[i], bhf[j], acc[i][j]);
#pragma unroll
            for (int j = 0; j < 2; j++)
                wmma::load_matrix_sync(blf[j], base + C1_BLO + (wn * 32 + j * 16) * C1_SA + kk, C1_SA);
#pragma unroll
            for (int i = 0; i < 4; i++)
#pragma unroll
                for (int j = 0; j < 2; j++)
                    wmma::mma_sync(acc[i][j], af[i], blf[j], acc[i][j]);
#pragma unroll
            for (int i = 0; i < 4; i++)
                wmma::load_matrix_sync(af[i], base + C1_ALO + (wm * 64 + i * 16) * C1_SA + kk, C1_SA);
#pragma unroll
            for (int i = 0; i < 4; i++)
#pragma unroll
                for (int j = 0; j < 2; j++)
                    wmma::mma_sync(acc[i][j], af[i], bhf[j], acc[i][j]);
        }
    };

    loadStage(0, 0);
    cp_commit();
    for (int kt = 0; kt < NKT1; kt++) {
        cp_wait<0>();
        __syncthreads();
        if (kt + 1 < NKT1) {
            loadStage((kt + 1) & 1, (kt + 1) * KC);
            cp_commit();
        }
        compute(kt & 1);
    }

    // Epilogue: acc -> smem col-major (element (m,n) at smf[n*128+m])
    __syncthreads();
#pragma unroll
    for (int i = 0; i < 4; i++)
#pragma unroll
        for (int j = 0; j < 2; j++)
            wmma::store_matrix_sync(smf + (wn * 32 + j * 16) * 128 + wm * 64 + i * 16,
                                    acc[i][j], 128, wmma::mem_col_major);
    __syncthreads();

    // BN + leaky, split to bf16 hi/lo, store [k][m]
#pragma unroll
    for (int it = 0; it < 16; it++) {
        int id = it * 256 + tid;
        int ncol = id >> 5;           // 0..127
        int r4 = (id & 31) * 4;       // 0..124
        float4 v = *(const float4*)(smf + ncol * 128 + r4);
        int n = n0 + ncol;
        float scale = gma[n] * rsqrtf(var[n] + 1e-5f);
        float bias = bet[n] - mea[n] * scale;
        float t;
        unsigned short h[4], l[4];
        t = v.x + bias; t = t > 0.f ? t : 0.1f * t; split_bf16(t, h[0], l[0]);
        t = v.y + bias; t = t > 0.f ? t : 0.1f * t; split_bf16(t, h[1], l[1]);
        t = v.z + bias; t = t > 0.f ? t : 0.1f * t; split_bf16(t, h[2], l[2]);
        t = v.w + bias; t = t > 0.f ? t : 0.1f * t; split_bf16(t, h[3], l[3]);
        size_t go = (size_t)n * MTOT + m0 + r4;
        *(uint2*)(g_xhi + go) = *(const uint2*)h;
        *(uint2*)(g_xlo + go) = *(const uint2*)l;
    }
}

// ---------------------------------------------------------------------------
// Conv2: wmma bf16x3 GEMM. CTA 128x128, 256 thr, warp 64x32, KC=32, 2-stage,
// 2 CTAs/SM. blockIdx.x = n-tile (fastest -> A tiles L2-shared by 4).
// ---------------------------------------------------------------------------
__global__ __launch_bounds__(256, 2)
void k_conv2_wm(const float* __restrict__ bias2) {
    extern __shared__ __align__(16) char smraw[];
    __nv_bfloat16* smb = (__nv_bfloat16*)smraw;
    float* smf = (float*)smraw;

    const int tid = threadIdx.x;
    const int w = tid >> 5;
    const int wm = w & 1, wn = w >> 1;
    const int n0 = blockIdx.x * 128;
    const int m0 = blockIdx.y * 128;

    const int akr = tid >> 3;            // 0..31
    const int aseg = (tid & 7) * 16;
    const int bkr = tid >> 3;
    const int bseg = (tid & 7) * 16;

    wmma::fragment<wmma::accumulator, 16, 16, 16, float> acc[4][2];
#pragma unroll
    for (int i = 0; i < 4; i++)
#pragma unroll
        for (int j = 0; j < 2; j++) wmma::fill_fragment(acc[i][j], 0.0f);

    auto loadStage = [&](int st, int kc) {
        __nv_bfloat16* base = smb + st * C2_STAGE;
        size_t ga = (size_t)(kc + akr) * MTOT + m0 + aseg;
        cp16(base + C2_AHI + akr * C2_SAM + aseg,     g_xhi + ga);
        cp16(base + C2_AHI + akr * C2_SAM + aseg + 8, g_xhi + ga + 8);
        cp16(base + C2_ALO + akr * C2_SAM + aseg,     g_xlo + ga);
        cp16(base + C2_ALO + akr * C2_SAM + aseg + 8, g_xlo + ga + 8);
        size_t gb = (size_t)(kc + bkr) * N2PAD + n0 + bseg;
        cp16(base + C2_BHI + bkr * C2_SBN + bseg,     g_w2hi + gb);
        cp16(base + C2_BHI + bkr * C2_SBN + bseg + 8, g_w2hi + gb + 8);
        cp16(base + C2_BLO + bkr * C2_SBN + bseg,     g_w2lo + gb);
        cp16(base + C2_BLO + bkr * C2_SBN + bseg + 8, g_w2lo + gb + 8);
    };

    auto compute = [&](int st) {
        const __nv_bfloat16* base = smb + st * C2_STAGE;
#pragma unroll
        for (int kk = 0; kk < KC; kk += 16) {
            wmma::fragment<wmma::matrix_a, 16, 16, 16, __nv_bfloat16, wmma::col_major> af[4];
            wmma::fragment<wmma::matrix_b, 16, 16, 16, __nv_bfloat16, wmma::row_major> bhf[2], blf[2];
#pragma unroll
            for (int i = 0; i < 4; i++)
                wmma::load_matrix_sync(af[i], base + C2_AHI + kk * C2_SAM + wm * 64 + i * 16, C2_SAM);
#pragma unroll
            for (int j = 0; j < 2; j++)
                wmma::load_matrix_sync(bhf[j], base + C2_BHI + kk * C2_SBN + wn * 32 + j * 16, C2_SBN);
#pragma unroll
            for (int i = 0; i < 4; i++)
#pragma unroll
                for (int j = 0; j < 2; j++)
                    wmma::mma_sync(acc[i][j], af[i], bhf[j], acc[i][j]);
#pragma unroll
            for (int j = 0; j < 2; j++)
                wmma::load_matrix_sync(blf[j], base + C2_BLO + kk * C2_SBN + wn * 32 + j * 16, C2_SBN);
#pragma unroll
            for (int i = 0; i < 4; i++)
#pragma unroll
                for (int j = 0; j < 2; j++)
                    wmma::mma_sync(acc[i][j], af[i], blf[j], acc[i][j]);
#pragma unroll
            for (int i = 0; i < 4; i++)
                wmma::load_matrix_sync(af[i], base + C2_ALO + kk * C2_SAM + wm * 64 + i * 16, C2_SAM);
#pragma unroll
            for (int i = 0; i < 4; i++)
#pragma unroll
                for (int j = 0; j < 2; j++)
                    wmma::mma_sync(acc[i][j], af[i], bhf[j], acc[i][j]);
        }
    };

    loadStage(0, 0);
    cp_commit();
    for (int kt = 0; kt < NKT2; kt++) {
        cp_wait<0>();
        __syncthreads();
        if (kt + 1 < NKT2) {
            loadStage((kt + 1) & 1, (kt + 1) * KC);
            cp_commit();
        }
        compute(kt & 1);
    }

    // Epilogue: acc -> smem row-major (element (m,n) at smf[m*128+n]), + bias -> g_p
    __syncthreads();
#pragma unroll
    for (int i = 0; i < 4; i++)
#pragma unroll
        for (int j = 0; j < 2; j++)
            wmma::store_matrix_sync(smf + (wm * 64 + i * 16) * 128 + wn * 32 + j * 16,
                                    acc[i][j], 128, wmma::mem_row_major);
    __syncthreads();

#pragma unroll
    for (int it = 0; it < 16; it++) {
        int id = it * 256 + tid;
        int mrow = id >> 5;          // 0..127
        int nc4 = (id & 31) * 4;
        float4 v = *(const float4*)(smf + mrow * 128 + nc4);
        int n = n0 + nc4;
        float* dst = g_p + (size_t)(m0 + mrow) * COUT2 + n;
        if (n + 0 < COUT2) dst[0] = v.x + bias2[n + 0];
        if (n + 1 < COUT2) dst[1] = v.y + bias2[n + 1];
        if (n + 2 < COUT2) dst[2] = v.z + bias2[n + 2];
        if (n + 3 < COUT2) dst[3] = v.w + bias2[n + 3];
    }
}

// ---------------------------------------------------------------------------
// Decode: one warp per (position, anchor)
// ---------------------------------------------------------------------------
__global__ void k_decode(float* __restrict__ out) {
    int g = blockIdx.x * (blockDim.x >> 5) + (threadIdx.x >> 5);
    int lane = threadIdx.x & 31;
    if (g >= MTOT * 5) return;
    int m = g / 5;
    int a = g - m * 5;
    const float* base = g_p + (size_t)m * COUT2 + a * 85;

    float t0 = base[0], t1 = base[1], t2 = base[2], t3 = base[3], t4 = base[4];

    float l0 = base[5 + lane];
    float l1 = base[5 + 32 + lane];
    float best = l0; int bi = lane;
    if (l1 > best) { best = l1; bi = lane + 32; }
    float l2 = -3.4e38f;
    if (lane < 16) {
        l2 = base[5 + 64 + lane];
        if (l2 > best) { best = l2; bi = lane + 64; }
    }
#pragma unroll
    for (int off = 16; off; off >>= 1) {
        float ob = __shfl_down_sync(0xffffffffu, best, off);
        int   oi = __shfl_down_sync(0xffffffffu, bi, off);
        if (ob > best || (ob == best && oi < bi)) { best = ob; bi = oi; }
    }
    float mx = __shfl_sync(0xffffffffu, best, 0);
    int gidx = __shfl_sync(0xffffffffu, bi, 0);

    float s = expf(l0 - mx) + expf(l1 - mx) + ((lane < 16) ? expf(l2 - mx) : 0.f);
#pragma unroll
    for (int off = 16; off; off >>= 1)
        s += __shfl_down_sync(0xffffffffu, s, off);

    if (lane == 0) {
        float bx = 1.f / (1.f + expf(-t0));
        float by = 1.f / (1.f + expf(-t1));
        float bw = expf(fminf(t2, 8.f));
        float bh = expf(fminf(t3, 8.f));
        float obj = 1.f / (1.f + expf(-t4));
        float score = obj / s;

        int b = m >> 10;
        int pos = m & 1023;
        int gy = pos >> 5, gx = pos & 31;
        float cx = (bx + (float)gx) * 32.f;
        float cy = (by + (float)gy) * 32.f;
        float pw = c_anc_w[a] * bw;
        float ph = c_anc_h[a] * bh;
        float x1 = fminf(fmaxf(cx - 0.5f * pw, 0.f), 1023.f);
        float y1 = fminf(fmaxf(cy - 0.5f * ph, 0.f), 1023.f);
        float x2 = fminf(fmaxf(cx + 0.5f * pw, 0.f), 1023.f);
        float y2 = fminf(fmaxf(cy + 0.5f * ph, 0.f), 1023.f);

        int idxo = pos * 5 + a;
        float* o5 = out + ((size_t)b * 5120 + idxo) * 5;
        o5[0] = x1; o5[1] = y1; o5[2] = x2; o5[3] = y2; o5[4] = score;
        out[(size_t)NBATCH * 5120 * 5 + (size_t)b * 5120 + idxo] = (float)gidx;
    }
}

// ---------------------------------------------------------------------------
extern "C" void kernel_launch(void* const* d_in, const int* in_sizes, int n_in,
                              void* d_out, int out_size) {
    const float* feat = (const float*)d_in[0];
    const float* w1   = (const float*)d_in[1];
    const float* gma  = (const float*)d_in[2];
    const float* bet  = (const float*)d_in[3];
    const float* mea  = (const float*)d_in[4];
    const float* var  = (const float*)d_in[5];
    const float* w2   = (const float*)d_in[6];
    const float* b2   = (const float*)d_in[7];
    float* out = (float*)d_out;

    static int attr_set = 0;
    if (!attr_set) {
        cudaFuncSetAttribute(k_conv1_wm, cudaFuncAttributeMaxDynamicSharedMemorySize, C1_SMEM_B);
        cudaFuncSetAttribute(k_conv2_wm, cudaFuncAttributeMaxDynamicSharedMemorySize, C2_SMEM_B);
        attr_set = 1;
    }

    k_split_w1<<<(COUT1 * K1 + 255) / 256, 256>>>(w1, gma, var);
    k_split_w2<<<dim3(K2 / 32, N2PAD / 32), dim3(32, 8)>>>(w2);
    k_conv1_wm<<<dim3(COUT1 / 128, MTOT / 128), 256, C1_SMEM_B>>>(feat, gma, bet, mea, var);
    k_conv2_wm<<<dim3(N2PAD / 128, MTOT / 128), 256, C2_SMEM_B>>>(b2);
    k_decode<<<(MTOT * 5 * 32 + 255) / 256, 256>>>(out);
}

// round 15
// speedup vs baseline: 1.8774x; 1.8071x over previous
#include <cuda_runtime.h>
#include <cuda_bf16.h>
#include <mma.h>
#include <math.h>
#include <stdint.h>

using namespace nvcuda;

// Problem constants
#define CIN    512
#define COUT1  1024
#define NBATCH 32
#define MTOT   32768         // NBATCH*32*32
#define COUT2  425
#define N2PAD  512
#define K2     1024
#define NKT2   (K2 / 32)     // 32

// Winograd F(2x2,3x3)
#define PT     8192          // tiles total (32 imgs * 16*16)
#define KW     512           // GEMM K (= CIN)
#define NKTW   (KW / 32)     // 16

// Winograd GEMM smem: A(V) [k][t] pitch 136 (32 rows), B(U) [n][k] pitch 40 (128 rows)
#define WG_PM      136
#define WG_PK      40
#define WG_AHI     0
#define WG_ALO     4352
#define WG_BHI     8704
#define WG_BLO     13824
#define WG_STAGE   18944
#define WG_SMEM_B  (2 * WG_STAGE * 2)     // 75776 bytes -> 2 CTAs/SM

// conv2 smem: A [k][m] pitch 136, B [k][n] pitch 136, 2 stages
#define C2_SAM     136
#define C2_SBN     136
#define C2_AHI     0
#define C2_ALO     4352
#define C2_BHI     8704
#define C2_BLO     13056
#define C2_STAGE   17408
#define C2_SMEM_B  (2 * C2_STAGE * 2)     // 69632 bytes -> 2 CTAs/SM

// Scratch (static device memory)
__device__ __align__(16) __nv_bfloat16 g_vhi[(size_t)16 * KW * PT];   // [xi][c][t]
__device__ __align__(16) __nv_bfloat16 g_vlo[(size_t)16 * KW * PT];
__device__ __align__(16) __nv_bfloat16 g_uhi[(size_t)16 * COUT1 * KW]; // [xi][n][c]
__device__ __align__(16) __nv_bfloat16 g_ulo[(size_t)16 * COUT1 * KW];
__device__ __align__(16) float g_m[(size_t)16 * COUT1 * PT];           // [xi][n][t]
__device__ __align__(16) __nv_bfloat16 g_xhi[(size_t)COUT1 * MTOT];    // [k][m]
__device__ __align__(16) __nv_bfloat16 g_xlo[(size_t)COUT1 * MTOT];
__device__ __align__(16) __nv_bfloat16 g_w2hi[(size_t)K2 * N2PAD];     // [k][n]
__device__ __align__(16) __nv_bfloat16 g_w2lo[(size_t)K2 * N2PAD];
__device__ float g_p[(size_t)MTOT * COUT2];                            // [m][n]

__constant__ float c_anc_w[5] = {42.f, 98.f, 180.f, 300.f, 400.f};
__constant__ float c_anc_h[5] = {45.f, 130.f, 260.f, 180.f, 400.f};

__device__ __forceinline__ void split_bf16(float v, unsigned short& h, unsigned short& l) {
    __nv_bfloat16 hb = __float2bfloat16_rn(v);
    h = __bfloat16_as_ushort(hb);
    l = __bfloat16_as_ushort(__float2bfloat16_rn(v - __bfloat162float(hb)));
}

__device__ __forceinline__ void cp16(const __nv_bfloat16* smem_dst, const void* gsrc) {
    uint32_t s = (uint32_t)__cvta_generic_to_shared(smem_dst);
    asm volatile("cp.async.cg.shared.global [%0], [%1], 16;" :: "r"(s), "l"(gsrc));
}
__device__ __forceinline__ void cp_commit() {
    asm volatile("cp.async.commit_group;" ::: "memory");
}
template <int N>
__device__ __forceinline__ void cp_wait() {
    asm volatile("cp.async.wait_group %0;" :: "n"(N) : "memory");
}

// ---------------------------------------------------------------------------
// Winograd weight transform: U = (G (w*scale) G^T), split, [xi][n][c]
// ---------------------------------------------------------------------------
__global__ __launch_bounds__(256)
void k_wino_w(const float* __restrict__ w,
              const float* __restrict__ gma, const float* __restrict__ var) {
    int id = blockIdx.x * 256 + threadIdx.x;
    if (id >= COUT1 * KW) return;
    int n = id >> 9, c = id & 511;
    float scale = gma[n] * rsqrtf(var[n] + 1e-5f);
    const float* g = w + ((size_t)n * KW + c) * 9;
    float a[3][3];
#pragma unroll
    for (int i = 0; i < 3; i++)
#pragma unroll
        for (int j = 0; j < 3; j++) a[i][j] = g[i * 3 + j] * scale;
    float q[4][3];
#pragma unroll
    for (int j = 0; j < 3; j++) {
        q[0][j] = a[0][j];
        q[1][j] = 0.5f * (a[0][j] + a[1][j] + a[2][j]);
        q[2][j] = 0.5f * (a[0][j] - a[1][j] + a[2][j]);
        q[3][j] = a[2][j];
    }
    float u[4][4];
#pragma unroll
    for (int i = 0; i < 4; i++) {
        u[i][0] = q[i][0];
        u[i][1] = 0.5f * (q[i][0] + q[i][1] + q[i][2]);
        u[i][2] = 0.5f * (q[i][0] - q[i][1] + q[i][2]);
        u[i][3] = q[i][2];
    }
    size_t o = ((size_t)n << 9) + c;
#pragma unroll
    for (int xi = 0; xi < 16; xi++) {
        unsigned short h, l;
        split_bf16(u[xi >> 2][xi & 3], h, l);
        g_uhi[(size_t)xi * COUT1 * KW + o] = __ushort_as_bfloat16(h);
        g_ulo[(size_t)xi * COUT1 * KW + o] = __ushort_as_bfloat16(l);
    }
}

__global__ void k_split_w2(const float* __restrict__ w) {
    __shared__ float tile[32][33];
    int kb = blockIdx.x * 32, nb = blockIdx.y * 32;
    int txd = threadIdx.x, tyd = threadIdx.y;
#pragma unroll
    for (int r = 0; r < 4; r++) {
        int n = nb + tyd + r * 8;
        tile[tyd + r * 8][txd] = (n < COUT2) ? w[(size_t)n * K2 + kb + txd] : 0.0f;
    }
    __syncthreads();
    int n = nb + txd;
#pragma unroll
    for (int r = 0; r < 4; r++) {
        int k = kb + tyd + r * 8;
        unsigned short h, l;
        split_bf16(tile[txd][tyd + r * 8], h, l);
        g_w2hi[(size_t)k * N2PAD + n] = __ushort_as_bfloat16(h);
        g_w2lo[(size_t)k * N2PAD + n] = __ushort_as_bfloat16(l);
    }
}

// ---------------------------------------------------------------------------
// Winograd input transform: V = B^T d B, split, [xi][c][t]
// ---------------------------------------------------------------------------
__global__ __launch_bounds__(256)
void k_wino_in(const float* __restrict__ feat) {
    int c = blockIdx.y;
    int t = blockIdx.x * 256 + threadIdx.x;   // 0..8191
    int img = t >> 8, tau = t & 255;
    int ty = tau >> 4, tx = tau & 15;
    const float* base = feat + (((size_t)img * CIN + c) << 10);
    int y0 = 2 * ty - 1, x0 = 2 * tx - 1;
    float d[4][4];
#pragma unroll
    for (int i = 0; i < 4; i++) {
        int yy = y0 + i;
        bool rok = (unsigned)yy < 32u;
#pragma unroll
        for (int j = 0; j < 4; j++) {
            int xx = x0 + j;
            d[i][j] = (rok && (unsigned)xx < 32u) ? base[(yy << 5) + xx] : 0.0f;
        }
    }
    float w0[4][4];
#pragma unroll
    for (int j = 0; j < 4; j++) {
        w0[0][j] = d[0][j] - d[2][j];
        w0[1][j] = d[1][j] + d[2][j];
        w0[2][j] = d[2][j] - d[1][j];
        w0[3][j] = d[1][j] - d[3][j];
    }
    float v[4][4];
#pragma unroll
    for (int i = 0; i < 4; i++) {
        v[i][0] = w0[i][0] - w0[i][2];
        v[i][1] = w0[i][1] + w0[i][2];
        v[i][2] = w0[i][2] - w0[i][1];
        v[i][3] = w0[i][1] - w0[i][3];
    }
    size_t o = ((size_t)c << 13) + t;
#pragma unroll
    for (int xi = 0; xi < 16; xi++) {
        unsigned short h, l;
        split_bf16(v[xi >> 2][xi & 3], h, l);
        g_vhi[(size_t)xi * KW * PT + o] = __ushort_as_bfloat16(h);
        g_vlo[(size_t)xi * KW * PT + o] = __ushort_as_bfloat16(l);
    }
}

// ---------------------------------------------------------------------------
// Winograd GEMM: M[xi][n][t] = sum_c U[xi][n][c] * V[xi][c][t].
// CTA 128t x 128n, 256 thr, warp 64x32, KC=32, 2-stage cp.async, 2 CTAs/SM.
// grid (n-tiles=8, t-tiles=64, xi=16).
// ---------------------------------------------------------------------------
__global__ __launch_bounds__(256, 2)
void k_wino_gemm() {
    extern __shared__ __align__(16) char smraw[];
    __nv_bfloat16* smb = (__nv_bfloat16*)smraw;
    float* smf = (float*)smraw;

    const int tid = threadIdx.x;
    const int w = tid >> 5;
    const int wm = w & 1, wn = w >> 1;
    const int n0 = blockIdx.x * 128;
    const int t0 = blockIdx.y * 128;
    const int xi = blockIdx.z;

    const __nv_bfloat16* vhi = g_vhi + (size_t)xi * KW * PT;
    const __nv_bfloat16* vlo = g_vlo + (size_t)xi * KW * PT;
    const __nv_bfloat16* uhi = g_uhi + (size_t)xi * COUT1 * KW;
    const __nv_bfloat16* ulo = g_ulo + (size_t)xi * COUT1 * KW;

    const int akr = tid >> 3;            // 0..31
    const int aseg = (tid & 7) * 16;
    const int brow = tid >> 1;           // 0..127
    const int bq = (tid & 1) * 16;

    wmma::fragment<wmma::accumulator, 16, 16, 16, float> acc[4][2];
#pragma unroll
    for (int i = 0; i < 4; i++)
#pragma unroll
        for (int j = 0; j < 2; j++) wmma::fill_fragment(acc[i][j], 0.0f);

    auto loadStage = [&](int st, int kc) {
        __nv_bfloat16* base = smb + st * WG_STAGE;
        size_t ga = (size_t)(kc + akr) * PT + t0 + aseg;
        cp16(base + WG_AHI + akr * WG_PM + aseg,     vhi + ga);
        cp16(base + WG_AHI + akr * WG_PM + aseg + 8, vhi + ga + 8);
        cp16(base + WG_ALO + akr * WG_PM + aseg,     vlo + ga);
        cp16(base + WG_ALO + akr * WG_PM + aseg + 8, vlo + ga + 8);
        size_t gb = (size_t)(n0 + brow) * KW + kc + bq;
        cp16(base + WG_BHI + brow * WG_PK + bq,     uhi + gb);
        cp16(base + WG_BHI + brow * WG_PK + bq + 8, uhi + gb + 8);
        cp16(base + WG_BLO + brow * WG_PK + bq,     ulo + gb);
        cp16(base + WG_BLO + brow * WG_PK + bq + 8, ulo + gb + 8);
    };

    auto compute = [&](int st) {
        const __nv_bfloat16* base = smb + st * WG_STAGE;
#pragma unroll
        for (int kk = 0; kk < 32; kk += 16) {
            wmma::fragment<wmma::matrix_a, 16, 16, 16, __nv_bfloat16, wmma::col_major> af[4];
            wmma::fragment<wmma::matrix_b, 16, 16, 16, __nv_bfloat16, wmma::col_major> bhf[2], blf[2];
#pragma unroll
            for (int i = 0; i < 4; i++)
                wmma::load_matrix_sync(af[i], base + WG_AHI + kk * WG_PM + wm * 64 + i * 16, WG_PM);
#pragma unroll
            for (int j = 0; j < 2; j++)
                wmma::load_matrix_sync(bhf[j], base + WG_BHI + (wn * 32 + j * 16) * WG_PK + kk, WG_PK);
#pragma unroll
            for (int i = 0; i < 4; i++)
#pragma unroll
                for (int j = 0; j < 2; j++)
                    wmma::mma_sync(acc[i][j], af[i], bhf[j], acc[i][j]);
#pragma unroll
            for (int j = 0; j < 2; j++)
                wmma::load_matrix_sync(blf[j], base + WG_BLO + (wn * 32 + j * 16) * WG_PK + kk, WG_PK);
#pragma unroll
            for (int i = 0; i < 4; i++)
#pragma unroll
                for (int j = 0; j < 2; j++)
                    wmma::mma_sync(acc[i][j], af[i], blf[j], acc[i][j]);
#pragma unroll
            for (int i = 0; i < 4; i++)
                wmma::load_matrix_sync(af[i], base + WG_ALO + kk * WG_PM + wm * 64 + i * 16, WG_PM);
#pragma unroll
            for (int i = 0; i < 4; i++)
#pragma unroll
                for (int j = 0; j < 2; j++)
                    wmma::mma_sync(acc[i][j], af[i], bhf[j], acc[i][j]);
        }
    };

    loadStage(0, 0);
    cp_commit();
    for (int kt = 0; kt < NKTW; kt++) {
        cp_wait<0>();
        __syncthreads();
        if (kt + 1 < NKTW) {
            loadStage((kt + 1) & 1, (kt + 1) * 32);
            cp_commit();
        }
        compute(kt & 1);
    }

    // Epilogue: acc -> smem col-major (element (t,n) at smf[n*128+t]) -> g_m
    __syncthreads();
#pragma unroll
    for (int i = 0; i < 4; i++)
#pragma unroll
        for (int j = 0; j < 2; j++)
            wmma::store_matrix_sync(smf + (wn * 32 + j * 16) * 128 + wm * 64 + i * 16,
                                    acc[i][j], 128, wmma::mem_col_major);
    __syncthreads();

#pragma unroll
    for (int it = 0; it < 16; it++) {
        int id = it * 256 + tid;
        int ncol = id >> 5;           // 0..127
        int r4 = (id & 31) * 4;       // 0..124
        float4 v = *(const float4*)(smf + ncol * 128 + r4);
        *(float4*)(g_m + (size_t)xi * COUT1 * PT + (size_t)(n0 + ncol) * PT + t0 + r4) = v;
    }
}

// ---------------------------------------------------------------------------
// Winograd output transform: Y = A^T M A + bias, leaky, split -> g_xhi/lo [k][m]
// ---------------------------------------------------------------------------
__global__ __launch_bounds__(256)
void k_wino_out(const float* __restrict__ gma, const float* __restrict__ bet,
                const float* __restrict__ mea, const float* __restrict__ var) {
    int id = blockIdx.x * 256 + threadIdx.x;   // n*8192 + t
    int n = id >> 13;
    int t = id & 8191;
    float m[4][4];
#pragma unroll
    for (int xi = 0; xi < 16; xi++)
        m[xi >> 2][xi & 3] = g_m[(size_t)xi * COUT1 * PT + (size_t)n * PT + t];
    float p0[4], p1[4];
#pragma unroll
    for (int j = 0; j < 4; j++) {
        p0[j] = m[0][j] + m[1][j] + m[2][j];
        p1[j] = m[1][j] - m[2][j] - m[3][j];
    }
    float y00 = p0[0] + p0[1] + p0[2];
    float y01 = p0[1] - p0[2] - p0[3];
    float y10 = p1[0] + p1[1] + p1[2];
    float y11 = p1[1] - p1[2] - p1[3];

    float scale = gma[n] * rsqrtf(var[n] + 1e-5f);
    float bias = bet[n] - mea[n] * scale;
    y00 += bias; y00 = y00 > 0.f ? y00 : 0.1f * y00;
    y01 += bias; y01 = y01 > 0.f ? y01 : 0.1f * y01;
    y10 += bias; y10 = y10 > 0.f ? y10 : 0.1f * y10;
    y11 += bias; y11 = y11 > 0.f ? y11 : 0.1f * y11;

    int img = t >> 8, tau = t & 255;
    int ty = tau >> 4, tx = tau & 15;
    int mbase = (img << 10) + (ty << 6) + (tx << 1);   // img*1024 + 2ty*32 + 2tx

    unsigned short h0, l0, h1, l1;
    uint32_t hp, lp;
    // row dy=0
    split_bf16(y00, h0, l0); split_bf16(y01, h1, l1);
    hp = (uint32_t)h0 | ((uint32_t)h1 << 16);
    lp = (uint32_t)l0 | ((uint32_t)l1 << 16);
    *(uint32_t*)(g_xhi + (size_t)n * MTOT + mbase) = hp;
    *(uint32_t*)(g_xlo + (size_t)n * MTOT + mbase) = lp;
    // row dy=1
    split_bf16(y10, h0, l0); split_bf16(y11, h1, l1);
    hp = (uint32_t)h0 | ((uint32_t)h1 << 16);
    lp = (uint32_t)l0 | ((uint32_t)l1 << 16);
    *(uint32_t*)(g_xhi + (size_t)n * MTOT + mbase + 32) = hp;
    *(uint32_t*)(g_xlo + (size_t)n * MTOT + mbase + 32) = lp;
}

// ---------------------------------------------------------------------------
// Conv2: wmma bf16x3 GEMM. CTA 128x128, 256 thr, warp 64x32, KC=32, 2-stage,
// 2 CTAs/SM. blockIdx.x = n-tile (fastest -> A tiles L2-shared by 4).
// ---------------------------------------------------------------------------
__global__ __launch_bounds__(256, 2)
void k_conv2_wm(const float* __restrict__ bias2) {
    extern __shared__ __align__(16) char smraw[];
    __nv_bfloat16* smb = (__nv_bfloat16*)smraw;
    float* smf = (float*)smraw;

    const int tid = threadIdx.x;
    const int w = tid >> 5;
    const int wm = w & 1, wn = w >> 1;
    const int n0 = blockIdx.x * 128;
    const int m0 = blockIdx.y * 128;

    const int akr = tid >> 3;            // 0..31
    const int aseg = (tid & 7) * 16;
    const int bkr = tid >> 3;
    const int bseg = (tid & 7) * 16;

    wmma::fragment<wmma::accumulator, 16, 16, 16, float> acc[4][2];
#pragma unroll
    for (int i = 0; i < 4; i++)
#pragma unroll
        for (int j = 0; j < 2; j++) wmma::fill_fragment(acc[i][j], 0.0f);

    auto loadStage = [&](int st, int kc) {
        __nv_bfloat16* base = smb + st * C2_STAGE;
        size_t ga = (size_t)(kc + akr) * MTOT + m0 + aseg;
        cp16(base + C2_AHI + akr * C2_SAM + aseg,     g_xhi + ga);
        cp16(base + C2_AHI + akr * C2_SAM + aseg + 8, g_xhi + ga + 8);
        cp16(base + C2_ALO + akr * C2_SAM + aseg,     g_xlo + ga);
        cp16(base + C2_ALO + akr * C2_SAM + aseg + 8, g_xlo + ga + 8);
        size_t gb = (size_t)(kc + bkr) * N2PAD + n0 + bseg;
        cp16(base + C2_BHI + bkr * C2_SBN + bseg,     g_w2hi + gb);
        cp16(base + C2_BHI + bkr * C2_SBN + bseg + 8, g_w2hi + gb + 8);
        cp16(base + C2_BLO + bkr * C2_SBN + bseg,     g_w2lo + gb);
        cp16(base + C2_BLO + bkr * C2_SBN + bseg + 8, g_w2lo + gb + 8);
    };

    auto compute = [&](int st) {
        const __nv_bfloat16* base = smb + st * C2_STAGE;
#pragma unroll
        for (int kk = 0; kk < 32; kk += 16) {
            wmma::fragment<wmma::matrix_a, 16, 16, 16, __nv_bfloat16, wmma::col_major> af[4];
            wmma::fragment<wmma::matrix_b, 16, 16, 16, __nv_bfloat16, wmma::row_major> bhf[2], blf[2];
#pragma unroll
            for (int i = 0; i < 4; i++)
                wmma::load_matrix_sync(af[i], base + C2_AHI + kk * C2_SAM + wm * 64 + i * 16, C2_SAM);
#pragma unroll
            for (int j = 0; j < 2; j++)
                wmma::load_matrix_sync(bhf[j], base + C2_BHI + kk * C2_SBN + wn * 32 + j * 16, C2_SBN);
#pragma unroll
            for (int i = 0; i < 4; i++)
#pragma unroll
                for (int j = 0; j < 2; j++)
                    wmma::mma_sync(acc[i][j], af[i], bhf[j], acc[i][j]);
#pragma unroll
            for (int j = 0; j < 2; j++)
                wmma::load_matrix_sync(blf[j], base + C2_BLO + kk * C2_SBN + wn * 32 + j * 16, C2_SBN);
#pragma unroll
            for (int i = 0; i < 4; i++)
#pragma unroll
                for (int j = 0; j < 2; j++)
                    wmma::mma_sync(acc[i][j], af[i], blf[j], acc[i][j]);
#pragma unroll
            for (int i = 0; i < 4; i++)
                wmma::load_matrix_sync(af[i], base + C2_ALO + kk * C2_SAM + wm * 64 + i * 16, C2_SAM);
#pragma unroll
            for (int i = 0; i < 4; i++)
#pragma unroll
                for (int j = 0; j < 2; j++)
                    wmma::mma_sync(acc[i][j], af[i], bhf[j], acc[i][j]);
        }
    };

    loadStage(0, 0);
    cp_commit();
    for (int kt = 0; kt < NKT2; kt++) {
        cp_wait<0>();
        __syncthreads();
        if (kt + 1 < NKT2) {
            loadStage((kt + 1) & 1, (kt + 1) * 32);
            cp_commit();
        }
        compute(kt & 1);
    }

    __syncthreads();
#pragma unroll
    for (int i = 0; i < 4; i++)
#pragma unroll
        for (int j = 0; j < 2; j++)
            wmma::store_matrix_sync(smf + (wm * 64 + i * 16) * 128 + wn * 32 + j * 16,
                                    acc[i][j], 128, wmma::mem_row_major);
    __syncthreads();

#pragma unroll
    for (int it = 0; it < 16; it++) {
        int id = it * 256 + tid;
        int mrow = id >> 5;          // 0..127
        int nc4 = (id & 31) * 4;
        float4 v = *(const float4*)(smf + mrow * 128 + nc4);
        int n = n0 + nc4;
        float* dst = g_p + (size_t)(m0 + mrow) * COUT2 + n;
        if (n + 0 < COUT2) dst[0] = v.x + bias2[n + 0];
        if (n + 1 < COUT2) dst[1] = v.y + bias2[n + 1];
        if (n + 2 < COUT2) dst[2] = v.z + bias2[n + 2];
        if (n + 3 < COUT2) dst[3] = v.w + bias2[n + 3];
    }
}

// ---------------------------------------------------------------------------
// Decode: one warp per (position, anchor)
// ---------------------------------------------------------------------------
__global__ void k_decode(float* __restrict__ out) {
    int g = blockIdx.x * (blockDim.x >> 5) + (threadIdx.x >> 5);
    int lane = threadIdx.x & 31;
    if (g >= MTOT * 5) return;
    int m = g / 5;
    int a = g - m * 5;
    const float* base = g_p + (size_t)m * COUT2 + a * 85;

    float t0 = base[0], t1 = base[1], t2 = base[2], t3 = base[3], t4 = base[4];

    float l0 = base[5 + lane];
    float l1 = base[5 + 32 + lane];
    float best = l0; int bi = lane;
    if (l1 > best) { best = l1; bi = lane + 32; }
    float l2 = -3.4e38f;
    if (lane < 16) {
        l2 = base[5 + 64 + lane];
        if (l2 > best) { best = l2; bi = lane + 64; }
    }
#pragma unroll
    for (int off = 16; off; off >>= 1) {
        float ob = __shfl_down_sync(0xffffffffu, best, off);
        int   oi = __shfl_down_sync(0xffffffffu, bi, off);
        if (ob > best || (ob == best && oi < bi)) { best = ob; bi = oi; }
    }
    float mx = __shfl_sync(0xffffffffu, best, 0);
    int gidx = __shfl_sync(0xffffffffu, bi, 0);

    float s = expf(l0 - mx) + expf(l1 - mx) + ((lane < 16) ? expf(l2 - mx) : 0.f);
#pragma unroll
    for (int off = 16; off; off >>= 1)
        s += __shfl_down_sync(0xffffffffu, s, off);

    if (lane == 0) {
        float bx = 1.f / (1.f + expf(-t0));
        float by = 1.f / (1.f + expf(-t1));
        float bw = expf(fminf(t2, 8.f));
        float bh = expf(fminf(t3, 8.f));
        float obj = 1.f / (1.f + expf(-t4));
        float score = obj / s;

        int b = m >> 10;
        int pos = m & 1023;
        int gy = pos >> 5, gx = pos & 31;
        float cx = (bx + (float)gx) * 32.f;
        float cy = (by + (float)gy) * 32.f;
        float pw = c_anc_w[a] * bw;
        float ph = c_anc_h[a] * bh;
        float x1 = fminf(fmaxf(cx - 0.5f * pw, 0.f), 1023.f);
        float y1 = fminf(fmaxf(cy - 0.5f * ph, 0.f), 1023.f);
        float x2 = fminf(fmaxf(cx + 0.5f * pw, 0.f), 1023.f);
        float y2 = fminf(fmaxf(cy + 0.5f * ph, 0.f), 1023.f);

        int idxo = pos * 5 + a;
        float* o5 = out + ((size_t)b * 5120 + idxo) * 5;
        o5[0] = x1; o5[1] = y1; o5[2] = x2; o5[3] = y2; o5[4] = score;
        out[(size_t)NBATCH * 5120 * 5 + (size_t)b * 5120 + idxo] = (float)gidx;
    }
}

// ---------------------------------------------------------------------------
extern "C" void kernel_launch(void* const* d_in, const int* in_sizes, int n_in,
                              void* d_out, int out_size) {
    const float* feat = (const float*)d_in[0];
    const float* w1   = (const float*)d_in[1];
    const float* gma  = (const float*)d_in[2];
    const float* bet  = (const float*)d_in[3];
    const float* mea  = (const float*)d_in[4];
    const float* var  = (const float*)d_in[5];
    const float* w2   = (const float*)d_in[6];
    const float* b2   = (const float*)d_in[7];
    float* out = (float*)d_out;

    static int attr_set = 0;
    if (!attr_set) {
        cudaFuncSetAttribute(k_wino_gemm, cudaFuncAttributeMaxDynamicSharedMemorySize, WG_SMEM_B);
        cudaFuncSetAttribute(k_conv2_wm, cudaFuncAttributeMaxDynamicSharedMemorySize, C2_SMEM_B);
        attr_set = 1;
    }

    k_wino_w<<<(COUT1 * KW + 255) / 256, 256>>>(w1, gma, var);
    k_split_w2<<<dim3(K2 / 32, N2PAD / 32), dim3(32, 8)>>>(w2);
    k_wino_in<<<dim3(PT / 256, KW), 256>>>(feat);
    k_wino_gemm<<<dim3(COUT1 / 128, PT / 128, 16), 256, WG_SMEM_B>>>();
    k_wino_out<<<(COUT1 * PT) / 256, 256>>>(gma, bet, mea, var);
    k_conv2_wm<<<dim3(N2PAD / 128, MTOT / 128), 256, C2_SMEM_B>>>(b2);
    k_decode<<<(MTOT * 5 * 32 + 255) / 256, 256>>>(out);
}